// round 12
// baseline (speedup 1.0000x reference)
#include <cuda_runtime.h>
#include <cstddef>

// Problem constants (fixed by the reference):
//   B_PAIRS=2048 pairs, each pair = 44 ligand nodes + 300 protein nodes (stride 344)
//   Only the ligand segment sums (even segments) feed the MLP.
//   MLP: 128 ->256 relu -> 128 relu -> 64 relu -> 1
#define B_PAIRS 2048
#define LIG     44
#define STRIDE  344
#define F_IN    128
#define N0      256
#define N1      128
#define N2      64
#define RTILE   4          // pairs per MLP block -> grid 512
#define THREADS 256

typedef unsigned long long u64;

// 1 MB scratch for the per-pair feature sums.
__device__ float g_xs[B_PAIRS * F_IN];

// ---------------- packed fp32x2 helpers (sm_103a FFMA2) --------------------
#define PACK_F32X2(d, lo, hi) \
    asm("mov.b64 %0, {%1, %2};" : "=l"(d) : "f"(lo), "f"(hi))
#define UNPACK_F32X2(lo, hi, v) \
    asm("mov.b64 {%0, %1}, %2;" : "=f"(lo), "=f"(hi) : "l"(v))
#define FMA_F32X2(d, a, b, c) \
    asm("fma.rn.f32x2 %0, %1, %2, %3;" : "=l"(d) : "l"(a), "l"(b), "l"(c))
#define ADD_F32X2(d, a, b) \
    asm("add.rn.f32x2 %0, %1, %2;" : "=l"(d) : "l"(a), "l"(b))

// ============================================================================
// Kernel A: ligand segment sum. One block per pair (hot 46 MB L2-resident,
// runs at the LTS cap).
// ============================================================================
__global__ void __launch_bounds__(THREADS)
seg_sum_kernel(const float* __restrict__ features)
{
    __shared__ float4 part[8][32];
    const int tid  = threadIdx.x;
    const int pair = blockIdx.x;
    const int c4   = tid & 31;
    const int g    = tid >> 5;

    const float4* src = reinterpret_cast<const float4*>(features)
                      + (size_t)pair * STRIDE * (F_IN / 4) + c4;
    float4 acc = make_float4(0.f, 0.f, 0.f, 0.f);
#pragma unroll
    for (int r = g; r < LIG; r += 8) {
        float4 v = __ldcs(src + (size_t)r * (F_IN / 4));
        acc.x += v.x; acc.y += v.y; acc.z += v.z; acc.w += v.w;
    }
    part[g][c4] = acc;
    __syncthreads();

    if (tid < 32) {
        float4 s = part[0][tid];
#pragma unroll
        for (int gg = 1; gg < 8; ++gg) {
            float4 v = part[gg][tid];
            s.x += v.x; s.y += v.y; s.z += v.z; s.w += v.w;
        }
        reinterpret_cast<float4*>(g_xs)[pair * (F_IN / 4) + tid] = s;
    }
}

// ============================================================================
// Kernel B: 4-layer MLP, RTILE=4 rows, grid=512, 256 threads.
// Activations raw row-pairs (u64 = rows (2rp,2rp+1); one LDS.128 = all 4
// rows). Weights LDG.128 (4 cols), dup-packed on the fly (ALU, free).
// Inner iter: 1 LDG.128 + 1 LDS.128 + 4 packs + 8 FFMA2 per 16 lane-MACs.
// acc[c*2+rp] = packed rows (2rp,2rp+1) of column 4ct+c.
// ============================================================================
__global__ void __launch_bounds__(THREADS)
mlp_kernel(const float* __restrict__ W0, const float* __restrict__ b0,
           const float* __restrict__ W1, const float* __restrict__ b1,
           const float* __restrict__ W2, const float* __restrict__ b2,
           const float* __restrict__ Wout, const float* __restrict__ bout,
           float* __restrict__ out)
{
    __shared__ __align__(16) u64  xsP[F_IN][RTILE / 2];  // 2 KB raw row-pairs
    __shared__ __align__(16) u64  h0P[N0][RTILE / 2];    // 4 KB
    __shared__ __align__(16) u64  h1P[N1][RTILE / 2];    // 2 KB
    __shared__ __align__(16) float h2T[N2][RTILE];       // 1 KB
    __shared__ __align__(16) u64  pbuf[1920];            // 15 KB partials

    const int tid = threadIdx.x;
    const int p0  = blockIdx.x * RTILE;

    // Load 4 summed rows. Raw layout: xsP[k][rp] viewed as float[k][4].
    if (tid < 128) {
        const int pp = tid & 3;
        const int c4 = tid >> 2;                 // 0..31
        float4 v = reinterpret_cast<const float4*>(g_xs)
                       [(size_t)(p0 + pp) * (F_IN / 4) + c4];
        float* xf = reinterpret_cast<float*>(&xsP[0][0]);
        xf[(c4 * 4 + 0) * RTILE + pp] = v.x;
        xf[(c4 * 4 + 1) * RTILE + pp] = v.y;
        xf[(c4 * 4 + 2) * RTILE + pp] = v.z;
        xf[(c4 * 4 + 3) * RTILE + pp] = v.w;
    }
    __syncthreads();

    // ======== Layer 0: [4,128]@[128,256]+b relu | 64 ct(4col) x 4 kq x 32 ===
    {
        const int ct = tid & 63;                 // cols 4ct..4ct+3
        const int kq = tid >> 6;                 // 0..3, 32 k each
        u64 acc[8];                              // [c][rp]
#pragma unroll
        for (int i = 0; i < 8; ++i) acc[i] = 0ull;
        const float* Wp = W0 + (size_t)(kq * 32) * N0 + 4 * ct;
#pragma unroll 8
        for (int kk = 0; kk < 32; ++kk) {
            float4 wv = *reinterpret_cast<const float4*>(Wp + (size_t)kk * N0);
            u64 wd0, wd1, wd2, wd3;
            PACK_F32X2(wd0, wv.x, wv.x);
            PACK_F32X2(wd1, wv.y, wv.y);
            PACK_F32X2(wd2, wv.z, wv.z);
            PACK_F32X2(wd3, wv.w, wv.w);
            ulonglong2 a = *reinterpret_cast<const ulonglong2*>(
                               &xsP[kq * 32 + kk][0]);
            FMA_F32X2(acc[0], a.x, wd0, acc[0]);
            FMA_F32X2(acc[1], a.y, wd0, acc[1]);
            FMA_F32X2(acc[2], a.x, wd1, acc[2]);
            FMA_F32X2(acc[3], a.y, wd1, acc[3]);
            FMA_F32X2(acc[4], a.x, wd2, acc[4]);
            FMA_F32X2(acc[5], a.y, wd2, acc[5]);
            FMA_F32X2(acc[6], a.x, wd3, acc[6]);
            FMA_F32X2(acc[7], a.y, wd3, acc[7]);
        }
        if (kq > 0) {
            u64* dst = &pbuf[((kq - 1) * 64 + ct) * 8];
#pragma unroll
            for (int i = 0; i < 8; i += 2)
                *reinterpret_cast<ulonglong2*>(dst + i) =
                    make_ulonglong2(acc[i], acc[i + 1]);
        }
        __syncthreads();
        if (kq == 0) {
#pragma unroll
            for (int t = 0; t < 3; ++t) {
                const u64* q = &pbuf[(t * 64 + ct) * 8];
#pragma unroll
                for (int i = 0; i < 8; i += 2) {
                    ulonglong2 qq = *reinterpret_cast<const ulonglong2*>(q + i);
                    ADD_F32X2(acc[i],     acc[i],     qq.x);
                    ADD_F32X2(acc[i + 1], acc[i + 1], qq.y);
                }
            }
            float4 bv = *reinterpret_cast<const float4*>(b0 + 4 * ct);
            u64 bb[4];
            PACK_F32X2(bb[0], bv.x, bv.x);
            PACK_F32X2(bb[1], bv.y, bv.y);
            PACK_F32X2(bb[2], bv.z, bv.z);
            PACK_F32X2(bb[3], bv.w, bv.w);
#pragma unroll
            for (int c = 0; c < 4; ++c) {
#pragma unroll
                for (int rp = 0; rp < 2; ++rp) {
                    u64 s = acc[c * 2 + rp];
                    ADD_F32X2(s, s, bb[c]);
                    float v0, v1; UNPACK_F32X2(v0, v1, s);
                    PACK_F32X2(s, fmaxf(v0, 0.f), fmaxf(v1, 0.f));
                    acc[c * 2 + rp] = s;
                }
                *reinterpret_cast<ulonglong2*>(&h0P[4 * ct + c][0]) =
                    make_ulonglong2(acc[c * 2], acc[c * 2 + 1]);
            }
        }
    }
    __syncthreads();

    // ======== Layer 1: [4,256]@[256,128]+b relu | 32 ct(4col) x 8 kq x 32 ===
    {
        const int ct = tid & 31;                 // cols 4ct..4ct+3
        const int kq = tid >> 5;                 // 0..7, 32 k each
        u64 acc[8];
#pragma unroll
        for (int i = 0; i < 8; ++i) acc[i] = 0ull;
        const float* Wp = W1 + (size_t)(kq * 32) * N1 + 4 * ct;
#pragma unroll 8
        for (int kk = 0; kk < 32; ++kk) {
            float4 wv = *reinterpret_cast<const float4*>(Wp + (size_t)kk * N1);
            u64 wd0, wd1, wd2, wd3;
            PACK_F32X2(wd0, wv.x, wv.x);
            PACK_F32X2(wd1, wv.y, wv.y);
            PACK_F32X2(wd2, wv.z, wv.z);
            PACK_F32X2(wd3, wv.w, wv.w);
            ulonglong2 a = *reinterpret_cast<const ulonglong2*>(
                               &h0P[kq * 32 + kk][0]);
            FMA_F32X2(acc[0], a.x, wd0, acc[0]);
            FMA_F32X2(acc[1], a.y, wd0, acc[1]);
            FMA_F32X2(acc[2], a.x, wd1, acc[2]);
            FMA_F32X2(acc[3], a.y, wd1, acc[3]);
            FMA_F32X2(acc[4], a.x, wd2, acc[4]);
            FMA_F32X2(acc[5], a.y, wd2, acc[5]);
            FMA_F32X2(acc[6], a.x, wd3, acc[6]);
            FMA_F32X2(acc[7], a.y, wd3, acc[7]);
        }
        if (kq > 0) {
            u64* dst = &pbuf[((kq - 1) * 32 + ct) * 8];
#pragma unroll
            for (int i = 0; i < 8; i += 2)
                *reinterpret_cast<ulonglong2*>(dst + i) =
                    make_ulonglong2(acc[i], acc[i + 1]);
        }
        __syncthreads();
        if (kq == 0) {
#pragma unroll
            for (int t = 0; t < 7; ++t) {
                const u64* q = &pbuf[(t * 32 + ct) * 8];
#pragma unroll
                for (int i = 0; i < 8; i += 2) {
                    ulonglong2 qq = *reinterpret_cast<const ulonglong2*>(q + i);
                    ADD_F32X2(acc[i],     acc[i],     qq.x);
                    ADD_F32X2(acc[i + 1], acc[i + 1], qq.y);
                }
            }
            float4 bv = *reinterpret_cast<const float4*>(b1 + 4 * ct);
            u64 bb[4];
            PACK_F32X2(bb[0], bv.x, bv.x);
            PACK_F32X2(bb[1], bv.y, bv.y);
            PACK_F32X2(bb[2], bv.z, bv.z);
            PACK_F32X2(bb[3], bv.w, bv.w);
#pragma unroll
            for (int c = 0; c < 4; ++c) {
#pragma unroll
                for (int rp = 0; rp < 2; ++rp) {
                    u64 s = acc[c * 2 + rp];
                    ADD_F32X2(s, s, bb[c]);
                    float v0, v1; UNPACK_F32X2(v0, v1, s);
                    PACK_F32X2(s, fmaxf(v0, 0.f), fmaxf(v1, 0.f));
                    acc[c * 2 + rp] = s;
                }
                *reinterpret_cast<ulonglong2*>(&h1P[4 * ct + c][0]) =
                    make_ulonglong2(acc[c * 2], acc[c * 2 + 1]);
            }
        }
    }
    __syncthreads();

    // ======== Layer 2: [4,128]@[128,64]+b relu | 16 ct(4col) x 16 kq x 8 ====
    {
        const int ct = tid & 15;                 // cols 4ct..4ct+3
        const int kq = tid >> 4;                 // 0..15, 8 k each
        u64 acc[8];
#pragma unroll
        for (int i = 0; i < 8; ++i) acc[i] = 0ull;
        const float* Wp = W2 + (size_t)(kq * 8) * N2 + 4 * ct;
#pragma unroll
        for (int kk = 0; kk < 8; ++kk) {
            float4 wv = *reinterpret_cast<const float4*>(Wp + (size_t)kk * N2);
            u64 wd0, wd1, wd2, wd3;
            PACK_F32X2(wd0, wv.x, wv.x);
            PACK_F32X2(wd1, wv.y, wv.y);
            PACK_F32X2(wd2, wv.z, wv.z);
            PACK_F32X2(wd3, wv.w, wv.w);
            ulonglong2 a = *reinterpret_cast<const ulonglong2*>(
                               &h1P[kq * 8 + kk][0]);
            FMA_F32X2(acc[0], a.x, wd0, acc[0]);
            FMA_F32X2(acc[1], a.y, wd0, acc[1]);
            FMA_F32X2(acc[2], a.x, wd1, acc[2]);
            FMA_F32X2(acc[3], a.y, wd1, acc[3]);
            FMA_F32X2(acc[4], a.x, wd2, acc[4]);
            FMA_F32X2(acc[5], a.y, wd2, acc[5]);
            FMA_F32X2(acc[6], a.x, wd3, acc[6]);
            FMA_F32X2(acc[7], a.y, wd3, acc[7]);
        }
        if (kq > 0) {
            u64* dst = &pbuf[((kq - 1) * 16 + ct) * 8];
#pragma unroll
            for (int i = 0; i < 8; i += 2)
                *reinterpret_cast<ulonglong2*>(dst + i) =
                    make_ulonglong2(acc[i], acc[i + 1]);
        }
        __syncthreads();
        if (kq == 0) {
#pragma unroll
            for (int t = 0; t < 15; ++t) {
                const u64* q = &pbuf[(t * 16 + ct) * 8];
#pragma unroll
                for (int i = 0; i < 8; i += 2) {
                    ulonglong2 qq = *reinterpret_cast<const ulonglong2*>(q + i);
                    ADD_F32X2(acc[i],     acc[i],     qq.x);
                    ADD_F32X2(acc[i + 1], acc[i + 1], qq.y);
                }
            }
            float4 bv = *reinterpret_cast<const float4*>(b2 + 4 * ct);
            u64 bb[4];
            PACK_F32X2(bb[0], bv.x, bv.x);
            PACK_F32X2(bb[1], bv.y, bv.y);
            PACK_F32X2(bb[2], bv.z, bv.z);
            PACK_F32X2(bb[3], bv.w, bv.w);
#pragma unroll
            for (int c = 0; c < 4; ++c)
#pragma unroll
                for (int rp = 0; rp < 2; ++rp) {
                    u64 s = acc[c * 2 + rp];
                    ADD_F32X2(s, s, bb[c]);
                    float v0, v1; UNPACK_F32X2(v0, v1, s);
                    h2T[4 * ct + c][2 * rp    ] = fmaxf(v0, 0.f);
                    h2T[4 * ct + c][2 * rp + 1] = fmaxf(v1, 0.f);
                }
        }
    }
    __syncthreads();

    // ======== Output: [4,64]@[64,1]+b  (first 4 warps = 4 rows) =============
    {
        const int warp = tid >> 5;
        const int lane = tid & 31;
        if (warp < RTILE) {
            float s = h2T[2 * lane][warp]     * Wout[2 * lane]
                    + h2T[2 * lane + 1][warp] * Wout[2 * lane + 1];
#pragma unroll
            for (int o = 16; o > 0; o >>= 1)
                s += __shfl_down_sync(0xffffffffu, s, o);
            if (lane == 0)
                out[p0 + warp] = s + bout[0];
        }
    }
}

// d_in order (metadata): [0] batch_num_nodes (unused), [1] features,
// [2] W0, [3] b0, [4] W1, [5] b1, [6] W2, [7] b2, [8] Wout, [9] bout.
extern "C" void kernel_launch(void* const* d_in, const int* in_sizes, int n_in,
                              void* d_out, int out_size)
{
    const float* features = (const float*)d_in[1];
    const float* W0   = (const float*)d_in[2];
    const float* b0   = (const float*)d_in[3];
    const float* W1   = (const float*)d_in[4];
    const float* b1   = (const float*)d_in[5];
    const float* W2   = (const float*)d_in[6];
    const float* b2   = (const float*)d_in[7];
    const float* Wout = (const float*)d_in[8];
    const float* bout = (const float*)d_in[9];
    float* out = (float*)d_out;

    seg_sum_kernel<<<B_PAIRS, THREADS>>>(features);
    mlp_kernel<<<B_PAIRS / RTILE, THREADS>>>(W0, b0, W1, b1, W2, b2,
                                             Wout, bout, out);
}